// round 4
// baseline (speedup 1.0000x reference)
#include <cuda_runtime.h>
#include <math.h>

// Fixed-shape problem: B=4, N=50000, E=800000, D=64
#define NN 50000
#define BB 4
#define DD 64
#define NR (NN * BB)          // 200000 rows
#define SCAN_B 196            // ceil(50000/256)
#define GEMM_B (NR / 64)      // 3125 blocks for gemm
#define FLAG_BIT 0x40000000

// Scratch (__device__ globals per allocation-free rule)
__device__ float4 g_xw[(size_t)NR * 16];        // linear output, (N,B,D) = 51.2 MB
__device__ float4 g_h1[(size_t)NR * 16];        // layer-1 activation, (N,B,D)
__device__ float  g_dis[NN];                    // rsqrt(deg+1)
__device__ int    g_deg[NN];                    // zero-initialized; re-zeroed each pass
__device__ int    g_off[NN + 1];                // CSR offsets (by target node)
__device__ int    g_cur[NN];                    // fill cursors
__device__ unsigned long long g_edge[800000];   // packed (src, nrm)
__device__ int    g_pub[SCAN_B];                // lookback publications

// ---------------------------------------------------------------------------
// degree count (vectorized) + scan-flag reset
// ---------------------------------------------------------------------------
__global__ __launch_bounds__(256) void count_k(const int* __restrict__ ei, int E) {
    const int t = blockIdx.x * blockDim.x + threadIdx.x;
    if (blockIdx.x == 0 && threadIdx.x < SCAN_B) g_pub[threadIdx.x] = 0;
    const int e4 = t * 4;
    if (e4 + 4 <= E) {
        const int4 c = __ldg((const int4*)(ei + E) + t);
        atomicAdd(&g_deg[c.x], 1);
        atomicAdd(&g_deg[c.y], 1);
        atomicAdd(&g_deg[c.z], 1);
        atomicAdd(&g_deg[c.w], 1);
    } else {
        for (int e = e4; e < E; e++) atomicAdd(&g_deg[ei[E + e]], 1);
    }
}

// ---------------------------------------------------------------------------
// single-pass exclusive scan (decoupled lookback over 196 blocks)
// also: emits g_dis, re-zeroes g_deg for next replay, writes g_off[NN]=E
// ---------------------------------------------------------------------------
__global__ __launch_bounds__(256) void scan_k(int E) {
    __shared__ int sh[256];
    __shared__ int s_prefix;
    const int tid = threadIdx.x;
    const int b   = blockIdx.x;
    const int idx = b * 256 + tid;

    int v = 0;
    if (idx < NN) {
        v = g_deg[idx];
        g_deg[idx] = 0;                       // re-zero for next replay
        g_dis[idx] = rsqrtf((float)(v + 1));  // +1 self-loop
    }
    sh[tid] = v;
    __syncthreads();
#pragma unroll
    for (int o = 1; o < 256; o <<= 1) {
        int t2 = (tid >= o) ? sh[tid - o] : 0;
        __syncthreads();
        sh[tid] += t2;
        __syncthreads();
    }
    const int incl = sh[tid];
    const int total = sh[255];

    if (tid == 0) {
        s_prefix = 0;
        __threadfence();
        atomicExch(&g_pub[b], total | FLAG_BIT);   // publish aggregate
        if (b == 0) g_off[NN] = E;
    }
    __syncthreads();

    // lookback: thread tid (< b) fetches predecessor tid's aggregate
    if (tid < b) {
        int p;
        do { p = atomicAdd(&g_pub[tid], 0); } while (!(p & FLAG_BIT));
        atomicAdd(&s_prefix, p & ~FLAG_BIT);
    }
    __syncthreads();

    if (idx < NN) {
        const int off = s_prefix + incl - v;   // global exclusive prefix
        g_off[idx] = off;
        g_cur[idx] = off;
    }
}

// ---------------------------------------------------------------------------
// GEMM body: 64 rows x 64 cols per 256-thread block, 2x8 register tile.
// XBND: x is (B,N,D); else (N,B,D).
// ---------------------------------------------------------------------------
template <bool XBND>
__device__ __forceinline__ void gemm_body(const float* __restrict__ x,
                                          const float* __restrict__ W,
                                          int blk) {
    __shared__ __align__(16) float Ws[64 * 68];
    __shared__ float xs[64 * 65];
    const int tid = threadIdx.x;

    for (int i = tid; i < 4096; i += 256)
        Ws[(i >> 6) * 68 + (i & 63)] = W[i];

    const int base = blk * 64;
    {
        const int rl = tid >> 6, d = tid & 63;
#pragma unroll
        for (int g = 0; g < 64; g += 4) {
            const int rr = base + g + rl;
            float v;
            if (XBND) {
                const int n = rr >> 2, bb = rr & 3;
                v = x[((size_t)bb * NN + n) * DD + d];
            } else {
                v = x[(size_t)rr * DD + d];
            }
            xs[(g + rl) * 65 + d] = v;
        }
    }
    __syncthreads();

    const int r2 = (tid >> 3) * 2;
    const int c8 = (tid & 7) * 8;
    float acc[2][8];
#pragma unroll
    for (int i = 0; i < 2; i++)
#pragma unroll
        for (int j = 0; j < 8; j++) acc[i][j] = 0.0f;

#pragma unroll 8
    for (int k = 0; k < 64; k++) {
        const float a0 = xs[r2 * 65 + k];
        const float a1 = xs[(r2 + 1) * 65 + k];
        const float4 w0 = *(const float4*)&Ws[k * 68 + c8];
        const float4 w1 = *(const float4*)&Ws[k * 68 + c8 + 4];
        acc[0][0] = fmaf(a0, w0.x, acc[0][0]);
        acc[0][1] = fmaf(a0, w0.y, acc[0][1]);
        acc[0][2] = fmaf(a0, w0.z, acc[0][2]);
        acc[0][3] = fmaf(a0, w0.w, acc[0][3]);
        acc[0][4] = fmaf(a0, w1.x, acc[0][4]);
        acc[0][5] = fmaf(a0, w1.y, acc[0][5]);
        acc[0][6] = fmaf(a0, w1.z, acc[0][6]);
        acc[0][7] = fmaf(a0, w1.w, acc[0][7]);
        acc[1][0] = fmaf(a1, w0.x, acc[1][0]);
        acc[1][1] = fmaf(a1, w0.y, acc[1][1]);
        acc[1][2] = fmaf(a1, w0.z, acc[1][2]);
        acc[1][3] = fmaf(a1, w0.w, acc[1][3]);
        acc[1][4] = fmaf(a1, w1.x, acc[1][4]);
        acc[1][5] = fmaf(a1, w1.y, acc[1][5]);
        acc[1][6] = fmaf(a1, w1.z, acc[1][6]);
        acc[1][7] = fmaf(a1, w1.w, acc[1][7]);
    }

    float* outp = (float*)g_xw;
#pragma unroll
    for (int i = 0; i < 2; i++) {
        const size_t row = (size_t)(base + r2 + i);
        *(float4*)&outp[row * DD + c8]     = make_float4(acc[i][0], acc[i][1], acc[i][2], acc[i][3]);
        *(float4*)&outp[row * DD + c8 + 4] = make_float4(acc[i][4], acc[i][5], acc[i][6], acc[i][7]);
    }
}

// fill body: scatter edge records into CSR slots
__device__ __forceinline__ void fill_body(const int* __restrict__ ei, int E, int blk) {
    const int e = blk * 256 + threadIdx.x;
    if (e >= E) return;
    const int r = ei[e];        // source
    const int c = ei[E + e];    // target
    const int pos = atomicAdd(&g_cur[c], 1);
    const float nm = g_dis[r] * g_dis[c];
    g_edge[pos] = (unsigned long long)(unsigned int)r |
                  ((unsigned long long)__float_as_uint(nm) << 32);
}

// layer-1 GEMM fused (by block range) with CSR fill — independent work
__global__ __launch_bounds__(256) void gemmfill_k(const float* __restrict__ x,
                                                  const float* __restrict__ W,
                                                  const int* __restrict__ ei, int E) {
    if (blockIdx.x < GEMM_B) gemm_body<true>(x, W, blockIdx.x);
    else                     fill_body(ei, E, blockIdx.x - GEMM_B);
}

__global__ __launch_bounds__(256) void gemm2_k(const float* __restrict__ x,
                                               const float* __restrict__ W) {
    gemm_body<false>(x, W, blockIdx.x);
}

// ---------------------------------------------------------------------------
// Fused aggregation: per target node (64 threads), self-loop + in-edge sum,
// +bias, tanh. Unroll-4 with batched edge-record loads (MLP=4).
// ---------------------------------------------------------------------------
template <bool FINAL>
__global__ __launch_bounds__(256) void agg_k(const float* __restrict__ bias,
                                             float* __restrict__ dst) {
    const int node = blockIdx.x * 4 + (threadIdx.x >> 6);
    const int lane = threadIdx.x & 63;
    if (node >= NN) return;

    const float4* __restrict__ xw = g_xw;
    const float dn = g_dis[node];
    const float sl = dn * dn;
    float4 acc = __ldg(xw + (size_t)node * 64 + lane);
    acc.x *= sl; acc.y *= sl; acc.z *= sl; acc.w *= sl;

    const int beg = g_off[node];
    const int end = g_off[node + 1];
    int j = beg;

    for (; j + 4 <= end; j += 4) {
        const unsigned long long e0 = __ldg(g_edge + j);
        const unsigned long long e1 = __ldg(g_edge + j + 1);
        const unsigned long long e2 = __ldg(g_edge + j + 2);
        const unsigned long long e3 = __ldg(g_edge + j + 3);
        const float4 v0 = __ldg(xw + (size_t)(unsigned int)(e0 & 0xffffffffu) * 64 + lane);
        const float4 v1 = __ldg(xw + (size_t)(unsigned int)(e1 & 0xffffffffu) * 64 + lane);
        const float4 v2 = __ldg(xw + (size_t)(unsigned int)(e2 & 0xffffffffu) * 64 + lane);
        const float4 v3 = __ldg(xw + (size_t)(unsigned int)(e3 & 0xffffffffu) * 64 + lane);
        const float n0 = __uint_as_float((unsigned int)(e0 >> 32));
        const float n1 = __uint_as_float((unsigned int)(e1 >> 32));
        const float n2 = __uint_as_float((unsigned int)(e2 >> 32));
        const float n3 = __uint_as_float((unsigned int)(e3 >> 32));
        acc.x = fmaf(v0.x, n0, acc.x); acc.y = fmaf(v0.y, n0, acc.y);
        acc.z = fmaf(v0.z, n0, acc.z); acc.w = fmaf(v0.w, n0, acc.w);
        acc.x = fmaf(v1.x, n1, acc.x); acc.y = fmaf(v1.y, n1, acc.y);
        acc.z = fmaf(v1.z, n1, acc.z); acc.w = fmaf(v1.w, n1, acc.w);
        acc.x = fmaf(v2.x, n2, acc.x); acc.y = fmaf(v2.y, n2, acc.y);
        acc.z = fmaf(v2.z, n2, acc.z); acc.w = fmaf(v2.w, n2, acc.w);
        acc.x = fmaf(v3.x, n3, acc.x); acc.y = fmaf(v3.y, n3, acc.y);
        acc.z = fmaf(v3.z, n3, acc.z); acc.w = fmaf(v3.w, n3, acc.w);
    }
    for (; j < end; j++) {
        const unsigned long long e = __ldg(g_edge + j);
        const float4 v = __ldg(xw + (size_t)(unsigned int)(e & 0xffffffffu) * 64 + lane);
        const float nm = __uint_as_float((unsigned int)(e >> 32));
        acc.x = fmaf(v.x, nm, acc.x); acc.y = fmaf(v.y, nm, acc.y);
        acc.z = fmaf(v.z, nm, acc.z); acc.w = fmaf(v.w, nm, acc.w);
    }

    const float4 bv = __ldg((const float4*)bias + (lane & 15));
    float4 o;
    o.x = tanhf(acc.x + bv.x);
    o.y = tanhf(acc.y + bv.y);
    o.z = tanhf(acc.z + bv.z);
    o.w = tanhf(acc.w + bv.w);

    if (FINAL) {
        const int b = lane >> 4;
        ((float4*)dst)[((size_t)b * NN + node) * 16 + (lane & 15)] = o;
    } else {
        ((float4*)dst)[(size_t)node * 64 + lane] = o;
    }
}

// ---------------------------------------------------------------------------
extern "C" void kernel_launch(void* const* d_in, const int* in_sizes, int n_in,
                              void* d_out, int out_size) {
    const float* h  = (const float*)d_in[1];
    const int*   ei = (const int*)d_in[2];
    const float* W1 = (const float*)d_in[3];
    const float* b1 = (const float*)d_in[4];
    const float* W2 = (const float*)d_in[5];
    const float* b2 = (const float*)d_in[6];
    float* out = (float*)d_out;

    const int E  = in_sizes[2] / 2;
    const int eB = (E + 255) / 256;                 // fill blocks
    const int cB = (E / 4 + 255) / 256 + 1;         // count blocks (4 edges/thread)
    const int aB = (NN + 3) / 4;                    // 12500

    count_k   <<<cB, 256>>>(ei, E);                       // 1
    scan_k    <<<SCAN_B, 256>>>(E);                       // 2
    gemmfill_k<<<GEMM_B + eB, 256>>>(h, W1, ei, E);       // 3 (gemm1 + fill)
    agg_k<false><<<aB, 256>>>(b1, (float*)g_h1);          // 4  <- profiled
    gemm2_k   <<<GEMM_B, 256>>>((const float*)g_h1, W2);  // 5
    agg_k<true> <<<aB, 256>>>(b2, out);                   // 6
}